// round 15
// baseline (speedup 1.0000x reference)
#include <cuda_runtime.h>
#include <cuda_fp16.h>
#include <cstdint>

// Problem shapes (fixed by the dataset)
#define M_DIM 8192
#define K_DIM 4096
#define N_DIM 4096
#define KB    32          // K / 128
#define NB    32          // N / 128

// ---------------------------------------------------------------------------
// Scratch (no cudaMalloc allowed). Quantized values stored as fp16 (ints
// -128..127 are exact in fp16) so the GEMM uses real HMMA hardware.
// ---------------------------------------------------------------------------
__device__ __align__(16) __half g_xq[(size_t)M_DIM * K_DIM];   // 67 MB
__device__ float                g_xs[(size_t)KB * M_DIM];      // 1 MB ([kb][m])
__device__ __align__(16) __half g_wq[(size_t)N_DIM * K_DIM];   // 33.5 MB
__device__ float                g_ws[NB * KB];                 // 4 KB

__device__ __forceinline__ uint32_t h2_bits(__half2 h) {
    return *reinterpret_cast<uint32_t*>(&h);
}

// ---------------------------------------------------------------------------
// Kernel 1: activation quant. One warp per (m, 4 adjacent kb blocks): MLP=4.
// (R13 best, unchanged.)
// ---------------------------------------------------------------------------
__global__ void quant_x_kernel(const float* __restrict__ x) {
    int gw   = (blockIdx.x * blockDim.x + threadIdx.x) >> 5;  // 0 .. M*KB/4-1
    int lane = threadIdx.x & 31;
    int m   = gw >> 3;            // 8 block-quads per row
    int kbq = (gw & 7) << 2;      // first kb of the quad

    const float4* p = reinterpret_cast<const float4*>(x + (size_t)m * K_DIM + kbq * 128);
    float4 v0 = __ldg(p + lane);
    float4 v1 = __ldg(p + 32 + lane);
    float4 v2 = __ldg(p + 64 + lane);
    float4 v3 = __ldg(p + 96 + lane);

    float a0 = fmaxf(fmaxf(fabsf(v0.x), fabsf(v0.y)), fmaxf(fabsf(v0.z), fabsf(v0.w)));
    float a1 = fmaxf(fmaxf(fabsf(v1.x), fabsf(v1.y)), fmaxf(fabsf(v1.z), fabsf(v1.w)));
    float a2 = fmaxf(fmaxf(fabsf(v2.x), fabsf(v2.y)), fmaxf(fabsf(v2.z), fabsf(v2.w)));
    float a3 = fmaxf(fmaxf(fabsf(v3.x), fabsf(v3.y)), fmaxf(fabsf(v3.z), fabsf(v3.w)));
    #pragma unroll
    for (int off = 16; off > 0; off >>= 1) {
        a0 = fmaxf(a0, __shfl_xor_sync(0xffffffffu, a0, off));
        a1 = fmaxf(a1, __shfl_xor_sync(0xffffffffu, a1, off));
        a2 = fmaxf(a2, __shfl_xor_sync(0xffffffffu, a2, off));
        a3 = fmaxf(a3, __shfl_xor_sync(0xffffffffu, a3, off));
    }

    float s0 = fmaxf(__fdiv_rn(a0, 127.0f), 1e-12f);
    float s1 = fmaxf(__fdiv_rn(a1, 127.0f), 1e-12f);
    float s2 = fmaxf(__fdiv_rn(a2, 127.0f), 1e-12f);
    float s3 = fmaxf(__fdiv_rn(a3, 127.0f), 1e-12f);

    uint2* o = reinterpret_cast<uint2*>(g_xq + (size_t)m * K_DIM + kbq * 128);
    {
        float q0 = fminf(fmaxf(rintf(__fdiv_rn(v0.x, s0)), -128.0f), 127.0f);
        float q1 = fminf(fmaxf(rintf(__fdiv_rn(v0.y, s0)), -128.0f), 127.0f);
        float q2 = fminf(fmaxf(rintf(__fdiv_rn(v0.z, s0)), -128.0f), 127.0f);
        float q3 = fminf(fmaxf(rintf(__fdiv_rn(v0.w, s0)), -128.0f), 127.0f);
        uint2 h; h.x = h2_bits(__floats2half2_rn(q0, q1));
                 h.y = h2_bits(__floats2half2_rn(q2, q3));
        o[lane] = h;
    }
    {
        float q0 = fminf(fmaxf(rintf(__fdiv_rn(v1.x, s1)), -128.0f), 127.0f);
        float q1 = fminf(fmaxf(rintf(__fdiv_rn(v1.y, s1)), -128.0f), 127.0f);
        float q2 = fminf(fmaxf(rintf(__fdiv_rn(v1.z, s1)), -128.0f), 127.0f);
        float q3 = fminf(fmaxf(rintf(__fdiv_rn(v1.w, s1)), -128.0f), 127.0f);
        uint2 h; h.x = h2_bits(__floats2half2_rn(q0, q1));
                 h.y = h2_bits(__floats2half2_rn(q2, q3));
        o[32 + lane] = h;
    }
    {
        float q0 = fminf(fmaxf(rintf(__fdiv_rn(v2.x, s2)), -128.0f), 127.0f);
        float q1 = fminf(fmaxf(rintf(__fdiv_rn(v2.y, s2)), -128.0f), 127.0f);
        float q2 = fminf(fmaxf(rintf(__fdiv_rn(v2.z, s2)), -128.0f), 127.0f);
        float q3 = fminf(fmaxf(rintf(__fdiv_rn(v2.w, s2)), -128.0f), 127.0f);
        uint2 h; h.x = h2_bits(__floats2half2_rn(q0, q1));
                 h.y = h2_bits(__floats2half2_rn(q2, q3));
        o[64 + lane] = h;
    }
    {
        float q0 = fminf(fmaxf(rintf(__fdiv_rn(v3.x, s3)), -128.0f), 127.0f);
        float q1 = fminf(fmaxf(rintf(__fdiv_rn(v3.y, s3)), -128.0f), 127.0f);
        float q2 = fminf(fmaxf(rintf(__fdiv_rn(v3.z, s3)), -128.0f), 127.0f);
        float q3 = fminf(fmaxf(rintf(__fdiv_rn(v3.w, s3)), -128.0f), 127.0f);
        uint2 h; h.x = h2_bits(__floats2half2_rn(q0, q1));
                 h.y = h2_bits(__floats2half2_rn(q2, q3));
        o[96 + lane] = h;
    }
    if (lane == 0) {
        g_xs[(size_t)kbq * M_DIM + m]       = s0;   // transposed for GEMM reads
        g_xs[(size_t)(kbq + 1) * M_DIM + m] = s1;
        g_xs[(size_t)(kbq + 2) * M_DIM + m] = s2;
        g_xs[(size_t)(kbq + 3) * M_DIM + m] = s3;
    }
}

// ---------------------------------------------------------------------------
// Kernel 2: weight quant. One 512-thread CTA per (nb, kb) 128x128 block.
// (R13 best, unchanged.)
// ---------------------------------------------------------------------------
__global__ void quant_w_kernel(const float* __restrict__ w) {
    int nb = blockIdx.x >> 5;
    int kb = blockIdx.x & 31;
    int t  = threadIdx.x;
    const float4* base = reinterpret_cast<const float4*>(
        w + (size_t)(nb * 128) * K_DIM + kb * 128);

    float4 vv[8];
    float a = 0.0f;
    #pragma unroll
    for (int i = 0; i < 8; i++) {
        int idx = i * 512 + t;
        int r   = idx >> 5;
        int c4  = idx & 31;
        vv[i] = __ldg(base + (size_t)r * (K_DIM / 4) + c4);
        a = fmaxf(a, fmaxf(fmaxf(fabsf(vv[i].x), fabsf(vv[i].y)),
                           fmaxf(fabsf(vv[i].z), fabsf(vv[i].w))));
    }
    #pragma unroll
    for (int off = 16; off > 0; off >>= 1)
        a = fmaxf(a, __shfl_xor_sync(0xffffffffu, a, off));
    __shared__ float red[16];
    if ((t & 31) == 0) red[t >> 5] = a;
    __syncthreads();
    float am = red[0];
    #pragma unroll
    for (int i = 1; i < 16; i++) am = fmaxf(am, red[i]);

    float s = fmaxf(__fdiv_rn(am, 127.0f), 1e-12f);

    __half* qbase = g_wq + (size_t)(nb * 128) * K_DIM + kb * 128;
    #pragma unroll
    for (int i = 0; i < 8; i++) {
        int idx = i * 512 + t;
        int r   = idx >> 5;
        int c4  = idx & 31;
        float q0 = fminf(fmaxf(rintf(__fdiv_rn(vv[i].x, s)), -128.0f), 127.0f);
        float q1 = fminf(fmaxf(rintf(__fdiv_rn(vv[i].y, s)), -128.0f), 127.0f);
        float q2 = fminf(fmaxf(rintf(__fdiv_rn(vv[i].z, s)), -128.0f), 127.0f);
        float q3 = fminf(fmaxf(rintf(__fdiv_rn(vv[i].w, s)), -128.0f), 127.0f);
        uint2 h;
        h.x = h2_bits(__floats2half2_rn(q0, q1));
        h.y = h2_bits(__floats2half2_rn(q2, q3));
        *reinterpret_cast<uint2*>(qbase + (size_t)r * K_DIM + c4 * 4) = h;
    }
    if (t == 0) g_ws[nb * KB + kb] = s;
}

// ---------------------------------------------------------------------------
// Kernel 3: R13 GEMM (128x128 tile, 8 warps, 3-stage spread cp.async,
// GROUP_M=16 swizzle, f32x2 packed promotion) with two register-neutral
// reorderings: (1) promotion FFMA2s interleaved into the kk==7 iteration so
// they hide under remaining MMA issue; (2) next-block scale LDGs prefetched
// before the barrier.
// ---------------------------------------------------------------------------
#define STAGES     3
#define TILE_BYTES 32768                       // 128 rows x 256 B (fp16)
#define STAGE_SZ   (2 * TILE_BYTES)            // A + B
#define GEMM_SMEM  (STAGES * STAGE_SZ)         // 196608
#define GRID_N     (N_DIM / 128)               // 32
#define GRID_M     (M_DIM / 128)               // 64
#define GROUP_M    16

__device__ __forceinline__ uint32_t smem_u32(const void* p) {
    return (uint32_t)__cvta_generic_to_shared(p);
}
__device__ __forceinline__ void cpa16(uint32_t s, const void* g) {
    asm volatile("cp.async.cg.shared.global [%0], [%1], 16;\n" :: "r"(s), "l"(g));
}
__device__ __forceinline__ void mma_f16(float c[4], const uint32_t a[4],
                                        uint32_t b0, uint32_t b1) {
    asm volatile(
        "mma.sync.aligned.m16n8k16.row.col.f32.f16.f16.f32 "
        "{%0,%1,%2,%3}, {%4,%5,%6,%7}, {%8,%9}, {%0,%1,%2,%3};\n"
        : "+f"(c[0]), "+f"(c[1]), "+f"(c[2]), "+f"(c[3])
        : "r"(a[0]), "r"(a[1]), "r"(a[2]), "r"(a[3]), "r"(b0), "r"(b1));
}
__device__ __forceinline__ void ldsm4(uint32_t r[4], uint32_t addr) {
    asm volatile("ldmatrix.sync.aligned.m8n8.x4.shared.b16 {%0,%1,%2,%3}, [%4];"
                 : "=r"(r[0]), "=r"(r[1]), "=r"(r[2]), "=r"(r[3]) : "r"(addr));
}
__device__ __forceinline__ unsigned long long pack2(float lo, float hi) {
    unsigned long long r;
    asm("mov.b64 %0, {%1, %2};" : "=l"(r) : "f"(lo), "f"(hi));
    return r;
}
__device__ __forceinline__ void unpack2(unsigned long long v, float& lo, float& hi) {
    asm("mov.b64 {%0, %1}, %2;" : "=f"(lo), "=f"(hi) : "l"(v));
}
// packed dual fp32 FMA: d.lo += a.lo*b.lo ; d.hi += a.hi*b.hi
__device__ __forceinline__ void fma2(unsigned long long& d, unsigned long long a,
                                     unsigned long long b) {
    asm("fma.rn.f32x2 %0, %1, %2, %0;" : "+l"(d) : "l"(a), "l"(b));
}

__global__ void __launch_bounds__(256, 1)
gemm_kernel(const float* __restrict__ bias, float* __restrict__ out) {
    extern __shared__ __align__(1024) char smem[];
    const uint32_t sb = smem_u32(smem);
    const int tid  = threadIdx.x;
    const int lane = tid & 31;
    const int w    = tid >> 5;

    // grid swizzle: 16 m-tiles per group -> B panel re-read 4x
    const int pid      = blockIdx.x;
    const int group_id = pid / (GROUP_M * GRID_N);
    const int first_m  = group_id * GROUP_M;
    const int gsize    = min(GRID_M - first_m, GROUP_M);
    const int bm       = first_m + (pid % gsize);
    const int bn       = (pid % (GROUP_M * GRID_N)) / gsize;

    const int m0 = bm * 128;
    const int n0 = bn * 128;
    const int nb = bn;
    const int wm   = w & 3;        // 4 warps along M (32 rows each)
    const int wn   = w >> 2;       // 2 warps along N (64 cols each)
    const int grp  = lane >> 2;    // 0..7
    const int tig  = lane & 3;     // 0..3
    const int j    = lane >> 3;    // ldmatrix matrix index 0..3
    const int rlo  = lane & 7;     // ldmatrix row-in-matrix

    // one 1/8 slice of a stage load (i in 0..7): 2 x cp.async 16B per thread
    auto load_part = [&](int stage, int kb, int i) {
        const __half* Ag = g_xq + (size_t)m0 * K_DIM + kb * 128;
        const __half* Bg = g_wq + (size_t)n0 * K_DIM + kb * 128;
        uint32_t As = sb + stage * STAGE_SZ;
        uint32_t Bs = As + TILE_BYTES;
        int id = i * 256 + tid;        // 0..2047 chunks of 16B
        int r  = id >> 4;              // row 0..127
        int c  = id & 15;              // chunk 0..15
        uint32_t so = r * 256 + (((c & 8) | ((c ^ r) & 7)) << 4);
        cpa16(As + so, Ag + (size_t)r * K_DIM + c * 8);
        cpa16(Bs + so, Bg + (size_t)r * K_DIM + c * 8);
    };
    auto load_stage = [&](int stage, int kb) {
        #pragma unroll
        for (int i = 0; i < 8; i++) load_part(stage, kb, i);
    };

    // fp32 accumulators as packed f32x2 pairs: [fm][fn][2]
    unsigned long long facc2[2][8][2];
    #pragma unroll
    for (int i = 0; i < 2; i++)
        #pragma unroll
        for (int jj = 0; jj < 8; jj++) {
            facc2[i][jj][0] = 0ULL;
            facc2[i][jj][1] = 0ULL;
        }

    load_stage(0, 0); asm volatile("cp.async.commit_group;");
    load_stage(1, 1); asm volatile("cp.async.commit_group;");

    // precomputed ldmatrix row bases (within a stage)
    const int arow = wm * 32 + (j & 1) * 8 + rlo;            // + fm*16
    const int brow = wn * 64 + ((j >> 1) << 3) + rlo;        // + fnp*16
    const int achk = (j >> 1);                               // + kk*2
    const int bchk = (j & 1);                                // + kk*2

    // scale-row base pointers for prefetching
    const int sr0 = m0 + wm * 32 + grp;        // fm=0 row
    const int sr1 = sr0 + 16;                  // fm=1 row

    // prefetch scales for kb=0 (hidden under prologue loads)
    float pre_ws  = g_ws[nb * KB];
    float pre_x00 = __ldg(&g_xs[(size_t)0 * M_DIM + sr0]);
    float pre_x01 = __ldg(&g_xs[(size_t)0 * M_DIM + sr0 + 8]);
    float pre_x10 = __ldg(&g_xs[(size_t)0 * M_DIM + sr1]);
    float pre_x11 = __ldg(&g_xs[(size_t)0 * M_DIM + sr1 + 8]);

    for (int kb = 0; kb < KB; kb++) {
        asm volatile("cp.async.wait_group 1;");
        __syncthreads();
        const uint32_t As = sb + (uint32_t)(kb % 3) * STAGE_SZ;
        const uint32_t Bs = As + TILE_BYTES;
        const bool pf = (kb + 2 < KB);
        const int  pfs = (kb + 2) % 3;

        // pack this block's scales (already prefetched pre-barrier)
        unsigned long long csp[2][2];
        {
            float cs00 = pre_x00 * pre_ws;
            float cs01 = pre_x01 * pre_ws;
            float cs10 = pre_x10 * pre_ws;
            float cs11 = pre_x11 * pre_ws;
            csp[0][0] = pack2(cs00, cs00);
            csp[0][1] = pack2(cs01, cs01);
            csp[1][0] = pack2(cs10, cs10);
            csp[1][1] = pack2(cs11, cs11);
        }
        // prefetch next block's scales (consumed after next barrier)
        if (kb + 1 < KB) {
            pre_ws  = g_ws[nb * KB + kb + 1];
            pre_x00 = __ldg(&g_xs[(size_t)(kb + 1) * M_DIM + sr0]);
            pre_x01 = __ldg(&g_xs[(size_t)(kb + 1) * M_DIM + sr0 + 8]);
            pre_x10 = __ldg(&g_xs[(size_t)(kb + 1) * M_DIM + sr1]);
            pre_x11 = __ldg(&g_xs[(size_t)(kb + 1) * M_DIM + sr1 + 8]);
        }

        float c[2][8][4];
        #pragma unroll
        for (int i = 0; i < 2; i++)
            #pragma unroll
            for (int jj = 0; jj < 8; jj++)
                #pragma unroll
                for (int k = 0; k < 4; k++) c[i][jj][k] = 0.0f;

        #pragma unroll
        for (int kk = 0; kk < 8; kk++) {
            // spread the next-stage global loads across the block (1 slice per kk)
            if (pf) load_part(pfs, kb + 2, kk);

            // A fragments: 2 x ldmatrix.x4 (m16k16 each)
            uint32_t a[2][4];
            #pragma unroll
            for (int fm = 0; fm < 2; fm++) {
                int row = arow + fm * 16;
                int ch  = kk * 2 + achk;
                ldsm4(a[fm], As + row * 256 + (((ch & 8) | ((ch ^ row) & 7)) << 4));
            }
            // B fragments + MMAs: 4 x ldmatrix.x4 (two n8k16 frags each).
            // On the final kk, promote each (fm, fnp) group right after its
            // MMAs so promotion issue hides under the remaining MMA issue.
            #pragma unroll
            for (int fnp = 0; fnp < 4; fnp++) {
                int row = brow + fnp * 16;
                int ch  = kk * 2 + bchk;
                uint32_t bf[4];
                ldsm4(bf, Bs + row * 256 + (((ch & 8) | ((ch ^ row) & 7)) << 4));
                #pragma unroll
                for (int fm = 0; fm < 2; fm++) {
                    mma_f16(c[fm][fnp * 2],     a[fm], bf[0], bf[1]);
                    mma_f16(c[fm][fnp * 2 + 1], a[fm], bf[2], bf[3]);
                }
                if (kk == 7) {
                    #pragma unroll
                    for (int fm = 0; fm < 2; fm++)
                        #pragma unroll
                        for (int q = 0; q < 2; q++) {
                            int fn = fnp * 2 + q;
                            fma2(facc2[fm][fn][0],
                                 pack2(c[fm][fn][0], c[fm][fn][1]), csp[fm][0]);
                            fma2(facc2[fm][fn][1],
                                 pack2(c[fm][fn][2], c[fm][fn][3]), csp[fm][1]);
                        }
                }
            }
        }

        asm volatile("cp.async.commit_group;");
    }

    // epilogue: unpack, add bias, store fp32
    #pragma unroll
    for (int fm = 0; fm < 2; fm++) {
        int r = m0 + wm * 32 + fm * 16 + grp;
        #pragma unroll
        for (int fn = 0; fn < 8; fn++) {
            int cc = n0 + wn * 64 + fn * 8 + tig * 2;
            float2 b2 = *reinterpret_cast<const float2*>(bias + cc);
            float f0, f1, f2, f3;
            unpack2(facc2[fm][fn][0], f0, f1);
            unpack2(facc2[fm][fn][1], f2, f3);
            float2 o0, o1;
            o0.x = f0 + b2.x;
            o0.y = f1 + b2.y;
            o1.x = f2 + b2.x;
            o1.y = f3 + b2.y;
            *reinterpret_cast<float2*>(out + (size_t)r * N_DIM + cc)       = o0;
            *reinterpret_cast<float2*>(out + (size_t)(r + 8) * N_DIM + cc) = o1;
        }
    }
}

// ---------------------------------------------------------------------------
extern "C" void kernel_launch(void* const* d_in, const int* in_sizes, int n_in,
                              void* d_out, int out_size) {
    const float* x    = (const float*)d_in[0];
    const float* wgt  = (const float*)d_in[1];
    const float* bias = (const float*)d_in[2];
    float* out        = (float*)d_out;

    quant_x_kernel<<<(M_DIM * KB / 4) / 8, 256>>>(x);
    quant_w_kernel<<<NB * KB, 512>>>(wgt);

    cudaFuncSetAttribute(gemm_kernel,
                         cudaFuncAttributeMaxDynamicSharedMemorySize, GEMM_SMEM);
    gemm_kernel<<<GRID_M * GRID_N, 256, GEMM_SMEM>>>(bias, out);
}

// round 16
// speedup vs baseline: 1.3216x; 1.3216x over previous
#include <cuda_runtime.h>
#include <cuda_fp16.h>
#include <cstdint>

// Problem shapes (fixed by the dataset)
#define M_DIM 8192
#define K_DIM 4096
#define N_DIM 4096
#define KB    32          // K / 128
#define NB    32          // N / 128

// ---------------------------------------------------------------------------
// Scratch (no cudaMalloc allowed). Quantized values stored as fp16 (ints
// -128..127 are exact in fp16) so the GEMM uses real HMMA hardware.
// ---------------------------------------------------------------------------
__device__ __align__(16) __half g_xq[(size_t)M_DIM * K_DIM];   // 67 MB
__device__ float                g_xs[(size_t)KB * M_DIM];      // 1 MB ([kb][m])
__device__ __align__(16) __half g_wq[(size_t)N_DIM * K_DIM];   // 33.5 MB
__device__ float                g_ws[NB * KB];                 // 4 KB

__device__ __forceinline__ uint32_t h2_bits(__half2 h) {
    return *reinterpret_cast<uint32_t*>(&h);
}

// ---------------------------------------------------------------------------
// Kernel 1: activation quant. One warp per (m, 4 adjacent kb blocks): MLP=4.
// ---------------------------------------------------------------------------
__global__ void quant_x_kernel(const float* __restrict__ x) {
    int gw   = (blockIdx.x * blockDim.x + threadIdx.x) >> 5;  // 0 .. M*KB/4-1
    int lane = threadIdx.x & 31;
    int m   = gw >> 3;            // 8 block-quads per row
    int kbq = (gw & 7) << 2;      // first kb of the quad

    const float4* p = reinterpret_cast<const float4*>(x + (size_t)m * K_DIM + kbq * 128);
    float4 v0 = __ldg(p + lane);
    float4 v1 = __ldg(p + 32 + lane);
    float4 v2 = __ldg(p + 64 + lane);
    float4 v3 = __ldg(p + 96 + lane);

    float a0 = fmaxf(fmaxf(fabsf(v0.x), fabsf(v0.y)), fmaxf(fabsf(v0.z), fabsf(v0.w)));
    float a1 = fmaxf(fmaxf(fabsf(v1.x), fabsf(v1.y)), fmaxf(fabsf(v1.z), fabsf(v1.w)));
    float a2 = fmaxf(fmaxf(fabsf(v2.x), fabsf(v2.y)), fmaxf(fabsf(v2.z), fabsf(v2.w)));
    float a3 = fmaxf(fmaxf(fabsf(v3.x), fabsf(v3.y)), fmaxf(fabsf(v3.z), fabsf(v3.w)));
    #pragma unroll
    for (int off = 16; off > 0; off >>= 1) {
        a0 = fmaxf(a0, __shfl_xor_sync(0xffffffffu, a0, off));
        a1 = fmaxf(a1, __shfl_xor_sync(0xffffffffu, a1, off));
        a2 = fmaxf(a2, __shfl_xor_sync(0xffffffffu, a2, off));
        a3 = fmaxf(a3, __shfl_xor_sync(0xffffffffu, a3, off));
    }

    float s0 = fmaxf(__fdiv_rn(a0, 127.0f), 1e-12f);
    float s1 = fmaxf(__fdiv_rn(a1, 127.0f), 1e-12f);
    float s2 = fmaxf(__fdiv_rn(a2, 127.0f), 1e-12f);
    float s3 = fmaxf(__fdiv_rn(a3, 127.0f), 1e-12f);

    uint2* o = reinterpret_cast<uint2*>(g_xq + (size_t)m * K_DIM + kbq * 128);
    {
        float q0 = fminf(fmaxf(rintf(__fdiv_rn(v0.x, s0)), -128.0f), 127.0f);
        float q1 = fminf(fmaxf(rintf(__fdiv_rn(v0.y, s0)), -128.0f), 127.0f);
        float q2 = fminf(fmaxf(rintf(__fdiv_rn(v0.z, s0)), -128.0f), 127.0f);
        float q3 = fminf(fmaxf(rintf(__fdiv_rn(v0.w, s0)), -128.0f), 127.0f);
        uint2 h; h.x = h2_bits(__floats2half2_rn(q0, q1));
                 h.y = h2_bits(__floats2half2_rn(q2, q3));
        o[lane] = h;
    }
    {
        float q0 = fminf(fmaxf(rintf(__fdiv_rn(v1.x, s1)), -128.0f), 127.0f);
        float q1 = fminf(fmaxf(rintf(__fdiv_rn(v1.y, s1)), -128.0f), 127.0f);
        float q2 = fminf(fmaxf(rintf(__fdiv_rn(v1.z, s1)), -128.0f), 127.0f);
        float q3 = fminf(fmaxf(rintf(__fdiv_rn(v1.w, s1)), -128.0f), 127.0f);
        uint2 h; h.x = h2_bits(__floats2half2_rn(q0, q1));
                 h.y = h2_bits(__floats2half2_rn(q2, q3));
        o[32 + lane] = h;
    }
    {
        float q0 = fminf(fmaxf(rintf(__fdiv_rn(v2.x, s2)), -128.0f), 127.0f);
        float q1 = fminf(fmaxf(rintf(__fdiv_rn(v2.y, s2)), -128.0f), 127.0f);
        float q2 = fminf(fmaxf(rintf(__fdiv_rn(v2.z, s2)), -128.0f), 127.0f);
        float q3 = fminf(fmaxf(rintf(__fdiv_rn(v2.w, s2)), -128.0f), 127.0f);
        uint2 h; h.x = h2_bits(__floats2half2_rn(q0, q1));
                 h.y = h2_bits(__floats2half2_rn(q2, q3));
        o[64 + lane] = h;
    }
    {
        float q0 = fminf(fmaxf(rintf(__fdiv_rn(v3.x, s3)), -128.0f), 127.0f);
        float q1 = fminf(fmaxf(rintf(__fdiv_rn(v3.y, s3)), -128.0f), 127.0f);
        float q2 = fminf(fmaxf(rintf(__fdiv_rn(v3.z, s3)), -128.0f), 127.0f);
        float q3 = fminf(fmaxf(rintf(__fdiv_rn(v3.w, s3)), -128.0f), 127.0f);
        uint2 h; h.x = h2_bits(__floats2half2_rn(q0, q1));
                 h.y = h2_bits(__floats2half2_rn(q2, q3));
        o[96 + lane] = h;
    }
    if (lane == 0) {
        g_xs[(size_t)kbq * M_DIM + m]       = s0;   // transposed for GEMM reads
        g_xs[(size_t)(kbq + 1) * M_DIM + m] = s1;
        g_xs[(size_t)(kbq + 2) * M_DIM + m] = s2;
        g_xs[(size_t)(kbq + 3) * M_DIM + m] = s3;
    }
}

// ---------------------------------------------------------------------------
// Kernel 2: weight quant. One 512-thread CTA per (nb, kb) 128x128 block.
// Single pass: 8 float4/thread in registers, warp+CTA amax, quantize.
// ---------------------------------------------------------------------------
__global__ void quant_w_kernel(const float* __restrict__ w) {
    int nb = blockIdx.x >> 5;
    int kb = blockIdx.x & 31;
    int t  = threadIdx.x;
    const float4* base = reinterpret_cast<const float4*>(
        w + (size_t)(nb * 128) * K_DIM + kb * 128);

    float4 vv[8];
    float a = 0.0f;
    #pragma unroll
    for (int i = 0; i < 8; i++) {
        int idx = i * 512 + t;
        int r   = idx >> 5;
        int c4  = idx & 31;
        vv[i] = __ldg(base + (size_t)r * (K_DIM / 4) + c4);
        a = fmaxf(a, fmaxf(fmaxf(fabsf(vv[i].x), fabsf(vv[i].y)),
                           fmaxf(fabsf(vv[i].z), fabsf(vv[i].w))));
    }
    #pragma unroll
    for (int off = 16; off > 0; off >>= 1)
        a = fmaxf(a, __shfl_xor_sync(0xffffffffu, a, off));
    __shared__ float red[16];
    if ((t & 31) == 0) red[t >> 5] = a;
    __syncthreads();
    float am = red[0];
    #pragma unroll
    for (int i = 1; i < 16; i++) am = fmaxf(am, red[i]);

    float s = fmaxf(__fdiv_rn(am, 127.0f), 1e-12f);

    __half* qbase = g_wq + (size_t)(nb * 128) * K_DIM + kb * 128;
    #pragma unroll
    for (int i = 0; i < 8; i++) {
        int idx = i * 512 + t;
        int r   = idx >> 5;
        int c4  = idx & 31;
        float q0 = fminf(fmaxf(rintf(__fdiv_rn(vv[i].x, s)), -128.0f), 127.0f);
        float q1 = fminf(fmaxf(rintf(__fdiv_rn(vv[i].y, s)), -128.0f), 127.0f);
        float q2 = fminf(fmaxf(rintf(__fdiv_rn(vv[i].z, s)), -128.0f), 127.0f);
        float q3 = fminf(fmaxf(rintf(__fdiv_rn(vv[i].w, s)), -128.0f), 127.0f);
        uint2 h;
        h.x = h2_bits(__floats2half2_rn(q0, q1));
        h.y = h2_bits(__floats2half2_rn(q2, q3));
        *reinterpret_cast<uint2*>(qbase + (size_t)r * K_DIM + c4 * 4) = h;
    }
    if (t == 0) g_ws[nb * KB + kb] = s;
}

// ---------------------------------------------------------------------------
// Kernel 3: fp16 GEMM on quantized values (exact: integer values, fp32
// accumulation, per-128-K-block sums < 2^24). 128x128 CTA tile, K-step 128,
// mma.sync.m16n8k16 + ldmatrix. Grid swizzle (GROUP_M=16); spread cp.async.
// Per-kb promotion uses packed fma.rn.f32x2 (FFMA2). (R13 best, exact.)
// ---------------------------------------------------------------------------
#define STAGES     3
#define TILE_BYTES 32768                       // 128 rows x 256 B (fp16)
#define STAGE_SZ   (2 * TILE_BYTES)            // A + B
#define GEMM_SMEM  (STAGES * STAGE_SZ)         // 196608
#define GRID_N     (N_DIM / 128)               // 32
#define GRID_M     (M_DIM / 128)               // 64
#define GROUP_M    16

__device__ __forceinline__ uint32_t smem_u32(const void* p) {
    return (uint32_t)__cvta_generic_to_shared(p);
}
__device__ __forceinline__ void cpa16(uint32_t s, const void* g) {
    asm volatile("cp.async.cg.shared.global [%0], [%1], 16;\n" :: "r"(s), "l"(g));
}
__device__ __forceinline__ void mma_f16(float c[4], const uint32_t a[4],
                                        uint32_t b0, uint32_t b1) {
    asm volatile(
        "mma.sync.aligned.m16n8k16.row.col.f32.f16.f16.f32 "
        "{%0,%1,%2,%3}, {%4,%5,%6,%7}, {%8,%9}, {%0,%1,%2,%3};\n"
        : "+f"(c[0]), "+f"(c[1]), "+f"(c[2]), "+f"(c[3])
        : "r"(a[0]), "r"(a[1]), "r"(a[2]), "r"(a[3]), "r"(b0), "r"(b1));
}
__device__ __forceinline__ void ldsm4(uint32_t r[4], uint32_t addr) {
    asm volatile("ldmatrix.sync.aligned.m8n8.x4.shared.b16 {%0,%1,%2,%3}, [%4];"
                 : "=r"(r[0]), "=r"(r[1]), "=r"(r[2]), "=r"(r[3]) : "r"(addr));
}
__device__ __forceinline__ unsigned long long pack2(float lo, float hi) {
    unsigned long long r;
    asm("mov.b64 %0, {%1, %2};" : "=l"(r) : "f"(lo), "f"(hi));
    return r;
}
__device__ __forceinline__ void unpack2(unsigned long long v, float& lo, float& hi) {
    asm("mov.b64 {%0, %1}, %2;" : "=f"(lo), "=f"(hi) : "l"(v));
}
// packed dual fp32 FMA: d.lo = a.lo*b.lo + d.lo ; d.hi = a.hi*b.hi + d.hi
__device__ __forceinline__ void fma2(unsigned long long& d, unsigned long long a,
                                     unsigned long long b) {
    asm("fma.rn.f32x2 %0, %1, %2, %0;" : "+l"(d) : "l"(a), "l"(b));
}

__global__ void __launch_bounds__(256, 1)
gemm_kernel(const float* __restrict__ bias, float* __restrict__ out) {
    extern __shared__ __align__(1024) char smem[];
    const uint32_t sb = smem_u32(smem);
    const int tid  = threadIdx.x;
    const int lane = tid & 31;
    const int w    = tid >> 5;

    // grid swizzle: 16 m-tiles per group -> B panel re-read 4x
    const int pid      = blockIdx.x;
    const int group_id = pid / (GROUP_M * GRID_N);
    const int first_m  = group_id * GROUP_M;
    const int gsize    = min(GRID_M - first_m, GROUP_M);
    const int bm       = first_m + (pid % gsize);
    const int bn       = (pid % (GROUP_M * GRID_N)) / gsize;

    const int m0 = bm * 128;
    const int n0 = bn * 128;
    const int nb = bn;
    const int wm   = w & 3;        // 4 warps along M (32 rows each)
    const int wn   = w >> 2;       // 2 warps along N (64 cols each)
    const int grp  = lane >> 2;    // 0..7
    const int tig  = lane & 3;     // 0..3
    const int j    = lane >> 3;    // ldmatrix matrix index 0..3
    const int rlo  = lane & 7;     // ldmatrix row-in-matrix

    // one 1/8 slice of a stage load (i in 0..7): 2 x cp.async 16B per thread
    auto load_part = [&](int stage, int kb, int i) {
        const __half* Ag = g_xq + (size_t)m0 * K_DIM + kb * 128;
        const __half* Bg = g_wq + (size_t)n0 * K_DIM + kb * 128;
        uint32_t As = sb + stage * STAGE_SZ;
        uint32_t Bs = As + TILE_BYTES;
        int id = i * 256 + tid;        // 0..2047 chunks of 16B
        int r  = id >> 4;              // row 0..127
        int c  = id & 15;              // chunk 0..15
        uint32_t so = r * 256 + (((c & 8) | ((c ^ r) & 7)) << 4);
        cpa16(As + so, Ag + (size_t)r * K_DIM + c * 8);
        cpa16(Bs + so, Bg + (size_t)r * K_DIM + c * 8);
    };
    auto load_stage = [&](int stage, int kb) {
        #pragma unroll
        for (int i = 0; i < 8; i++) load_part(stage, kb, i);
    };

    // fp32 accumulators as packed f32x2 pairs: [fm][fn][2] (lo pair, hi pair)
    unsigned long long facc2[2][8][2];
    #pragma unroll
    for (int i = 0; i < 2; i++)
        #pragma unroll
        for (int jj = 0; jj < 8; jj++) {
            facc2[i][jj][0] = 0ULL;
            facc2[i][jj][1] = 0ULL;
        }

    load_stage(0, 0); asm volatile("cp.async.commit_group;");
    load_stage(1, 1); asm volatile("cp.async.commit_group;");

    // precomputed ldmatrix row bases (within a stage)
    const int arow = wm * 32 + (j & 1) * 8 + rlo;            // + fm*16
    const int brow = wn * 64 + ((j >> 1) << 3) + rlo;        // + fnp*16
    const int achk = (j >> 1);                               // + kk*2
    const int bchk = (j & 1);                                // + kk*2

    for (int kb = 0; kb < KB; kb++) {
        asm volatile("cp.async.wait_group 1;");
        __syncthreads();
        const uint32_t As = sb + (uint32_t)(kb % 3) * STAGE_SZ;
        const uint32_t Bs = As + TILE_BYTES;
        const bool pf = (kb + 2 < KB);
        const int  pfs = (kb + 2) % 3;

        // per-kb combined scales, packed for f32x2 promotion
        const float wsv = g_ws[nb * KB + kb];
        unsigned long long csp[2][2];
        #pragma unroll
        for (int fm = 0; fm < 2; fm++) {
            int r = m0 + wm * 32 + fm * 16 + grp;
            float cs0 = __ldg(&g_xs[(size_t)kb * M_DIM + r])     * wsv;
            float cs1 = __ldg(&g_xs[(size_t)kb * M_DIM + r + 8]) * wsv;
            csp[fm][0] = pack2(cs0, cs0);
            csp[fm][1] = pack2(cs1, cs1);
        }

        float c[2][8][4];
        #pragma unroll
        for (int i = 0; i < 2; i++)
            #pragma unroll
            for (int jj = 0; jj < 8; jj++)
                #pragma unroll
                for (int k = 0; k < 4; k++) c[i][jj][k] = 0.0f;

        #pragma unroll
        for (int kk = 0; kk < 8; kk++) {
            // spread the next-stage global loads across the block (1 slice per kk)
            if (pf) load_part(pfs, kb + 2, kk);

            // A fragments: 2 x ldmatrix.x4 (m16k16 each)
            uint32_t a[2][4];
            #pragma unroll
            for (int fm = 0; fm < 2; fm++) {
                int row = arow + fm * 16;
                int ch  = kk * 2 + achk;
                ldsm4(a[fm], As + row * 256 + (((ch & 8) | ((ch ^ row) & 7)) << 4));
            }
            // B fragments + MMAs: 4 x ldmatrix.x4 (two n8k16 frags each)
            #pragma unroll
            for (int fnp = 0; fnp < 4; fnp++) {
                int row = brow + fnp * 16;
                int ch  = kk * 2 + bchk;
                uint32_t bf[4];
                ldsm4(bf, Bs + row * 256 + (((ch & 8) | ((ch ^ row) & 7)) << 4));
                #pragma unroll
                for (int fm = 0; fm < 2; fm++) {
                    mma_f16(c[fm][fnp * 2],     a[fm], bf[0], bf[1]);
                    mma_f16(c[fm][fnp * 2 + 1], a[fm], bf[2], bf[3]);
                }
            }
        }

        // exact per-kb promotion, packed: facc2 += csp * c (dual IEEE fp32 FMA)
        #pragma unroll
        for (int fm = 0; fm < 2; fm++)
            #pragma unroll
            for (int fn = 0; fn < 8; fn++) {
                fma2(facc2[fm][fn][0], pack2(c[fm][fn][0], c[fm][fn][1]), csp[fm][0]);
                fma2(facc2[fm][fn][1], pack2(c[fm][fn][2], c[fm][fn][3]), csp[fm][1]);
            }

        asm volatile("cp.async.commit_group;");
    }

    // epilogue: unpack, add bias, store fp32
    #pragma unroll
    for (int fm = 0; fm < 2; fm++) {
        int r = m0 + wm * 32 + fm * 16 + grp;
        #pragma unroll
        for (int fn = 0; fn < 8; fn++) {
            int cc = n0 + wn * 64 + fn * 8 + tig * 2;
            float2 b2 = *reinterpret_cast<const float2*>(bias + cc);
            float f0, f1, f2, f3;
            unpack2(facc2[fm][fn][0], f0, f1);
            unpack2(facc2[fm][fn][1], f2, f3);
            float2 o0, o1;
            o0.x = f0 + b2.x;
            o0.y = f1 + b2.y;
            o1.x = f2 + b2.x;
            o1.y = f3 + b2.y;
            *reinterpret_cast<float2*>(out + (size_t)r * N_DIM + cc)       = o0;
            *reinterpret_cast<float2*>(out + (size_t)(r + 8) * N_DIM + cc) = o1;
        }
    }
}

// ---------------------------------------------------------------------------
extern "C" void kernel_launch(void* const* d_in, const int* in_sizes, int n_in,
                              void* d_out, int out_size) {
    const float* x    = (const float*)d_in[0];
    const float* wgt  = (const float*)d_in[1];
    const float* bias = (const float*)d_in[2];
    float* out        = (float*)d_out;

    quant_x_kernel<<<(M_DIM * KB / 4) / 8, 256>>>(x);
    quant_w_kernel<<<NB * KB, 512>>>(wgt);

    cudaFuncSetAttribute(gemm_kernel,
                         cudaFuncAttributeMaxDynamicSharedMemorySize, GEMM_SMEM);
    gemm_kernel<<<GRID_M * GRID_N, 256, GEMM_SMEM>>>(bias, out);
}

// round 17
// speedup vs baseline: 1.3220x; 1.0003x over previous
#include <cuda_runtime.h>
#include <cuda_fp16.h>
#include <cstdint>

// Problem shapes (fixed by the dataset)
#define M_DIM 8192
#define K_DIM 4096
#define N_DIM 4096
#define KB    32          // K / 128
#define NB    32          // N / 128

// ---------------------------------------------------------------------------
// Scratch (no cudaMalloc allowed). Quantized values stored as fp16 (ints
// -128..127 are exact in fp16) so the GEMM uses real HMMA hardware.
// ---------------------------------------------------------------------------
__device__ __align__(16) __half g_xq[(size_t)M_DIM * K_DIM];   // 67 MB
__device__ float                g_xs[(size_t)KB * M_DIM];      // 1 MB ([kb][m])
__device__ __align__(16) __half g_wq[(size_t)N_DIM * K_DIM];   // 33.5 MB
__device__ float                g_ws[NB * KB];                 // 4 KB

__device__ __forceinline__ uint32_t h2_bits(__half2 h) {
    return *reinterpret_cast<uint32_t*>(&h);
}

// ---------------------------------------------------------------------------
// Kernel 1: activation quant. One warp per (m, 4 adjacent kb blocks): MLP=4.
// ---------------------------------------------------------------------------
__global__ void quant_x_kernel(const float* __restrict__ x) {
    int gw   = (blockIdx.x * blockDim.x + threadIdx.x) >> 5;  // 0 .. M*KB/4-1
    int lane = threadIdx.x & 31;
    int m   = gw >> 3;            // 8 block-quads per row
    int kbq = (gw & 7) << 2;      // first kb of the quad

    const float4* p = reinterpret_cast<const float4*>(x + (size_t)m * K_DIM + kbq * 128);
    float4 v0 = __ldg(p + lane);
    float4 v1 = __ldg(p + 32 + lane);
    float4 v2 = __ldg(p + 64 + lane);
    float4 v3 = __ldg(p + 96 + lane);

    float a0 = fmaxf(fmaxf(fabsf(v0.x), fabsf(v0.y)), fmaxf(fabsf(v0.z), fabsf(v0.w)));
    float a1 = fmaxf(fmaxf(fabsf(v1.x), fabsf(v1.y)), fmaxf(fabsf(v1.z), fabsf(v1.w)));
    float a2 = fmaxf(fmaxf(fabsf(v2.x), fabsf(v2.y)), fmaxf(fabsf(v2.z), fabsf(v2.w)));
    float a3 = fmaxf(fmaxf(fabsf(v3.x), fabsf(v3.y)), fmaxf(fabsf(v3.z), fabsf(v3.w)));
    #pragma unroll
    for (int off = 16; off > 0; off >>= 1) {
        a0 = fmaxf(a0, __shfl_xor_sync(0xffffffffu, a0, off));
        a1 = fmaxf(a1, __shfl_xor_sync(0xffffffffu, a1, off));
        a2 = fmaxf(a2, __shfl_xor_sync(0xffffffffu, a2, off));
        a3 = fmaxf(a3, __shfl_xor_sync(0xffffffffu, a3, off));
    }

    float s0 = fmaxf(__fdiv_rn(a0, 127.0f), 1e-12f);
    float s1 = fmaxf(__fdiv_rn(a1, 127.0f), 1e-12f);
    float s2 = fmaxf(__fdiv_rn(a2, 127.0f), 1e-12f);
    float s3 = fmaxf(__fdiv_rn(a3, 127.0f), 1e-12f);

    uint2* o = reinterpret_cast<uint2*>(g_xq + (size_t)m * K_DIM + kbq * 128);
    {
        float q0 = fminf(fmaxf(rintf(__fdiv_rn(v0.x, s0)), -128.0f), 127.0f);
        float q1 = fminf(fmaxf(rintf(__fdiv_rn(v0.y, s0)), -128.0f), 127.0f);
        float q2 = fminf(fmaxf(rintf(__fdiv_rn(v0.z, s0)), -128.0f), 127.0f);
        float q3 = fminf(fmaxf(rintf(__fdiv_rn(v0.w, s0)), -128.0f), 127.0f);
        uint2 h; h.x = h2_bits(__floats2half2_rn(q0, q1));
                 h.y = h2_bits(__floats2half2_rn(q2, q3));
        o[lane] = h;
    }
    {
        float q0 = fminf(fmaxf(rintf(__fdiv_rn(v1.x, s1)), -128.0f), 127.0f);
        float q1 = fminf(fmaxf(rintf(__fdiv_rn(v1.y, s1)), -128.0f), 127.0f);
        float q2 = fminf(fmaxf(rintf(__fdiv_rn(v1.z, s1)), -128.0f), 127.0f);
        float q3 = fminf(fmaxf(rintf(__fdiv_rn(v1.w, s1)), -128.0f), 127.0f);
        uint2 h; h.x = h2_bits(__floats2half2_rn(q0, q1));
                 h.y = h2_bits(__floats2half2_rn(q2, q3));
        o[32 + lane] = h;
    }
    {
        float q0 = fminf(fmaxf(rintf(__fdiv_rn(v2.x, s2)), -128.0f), 127.0f);
        float q1 = fminf(fmaxf(rintf(__fdiv_rn(v2.y, s2)), -128.0f), 127.0f);
        float q2 = fminf(fmaxf(rintf(__fdiv_rn(v2.z, s2)), -128.0f), 127.0f);
        float q3 = fminf(fmaxf(rintf(__fdiv_rn(v2.w, s2)), -128.0f), 127.0f);
        uint2 h; h.x = h2_bits(__floats2half2_rn(q0, q1));
                 h.y = h2_bits(__floats2half2_rn(q2, q3));
        o[64 + lane] = h;
    }
    {
        float q0 = fminf(fmaxf(rintf(__fdiv_rn(v3.x, s3)), -128.0f), 127.0f);
        float q1 = fminf(fmaxf(rintf(__fdiv_rn(v3.y, s3)), -128.0f), 127.0f);
        float q2 = fminf(fmaxf(rintf(__fdiv_rn(v3.z, s3)), -128.0f), 127.0f);
        float q3 = fminf(fmaxf(rintf(__fdiv_rn(v3.w, s3)), -128.0f), 127.0f);
        uint2 h; h.x = h2_bits(__floats2half2_rn(q0, q1));
                 h.y = h2_bits(__floats2half2_rn(q2, q3));
        o[96 + lane] = h;
    }
    if (lane == 0) {
        g_xs[(size_t)kbq * M_DIM + m]       = s0;   // transposed for GEMM reads
        g_xs[(size_t)(kbq + 1) * M_DIM + m] = s1;
        g_xs[(size_t)(kbq + 2) * M_DIM + m] = s2;
        g_xs[(size_t)(kbq + 3) * M_DIM + m] = s3;
    }
}

// ---------------------------------------------------------------------------
// Kernel 2: weight quant. One 512-thread CTA per (nb, kb) 128x128 block.
// Single pass: 8 float4/thread in registers, warp+CTA amax, quantize.
// ---------------------------------------------------------------------------
__global__ void quant_w_kernel(const float* __restrict__ w) {
    int nb = blockIdx.x >> 5;
    int kb = blockIdx.x & 31;
    int t  = threadIdx.x;
    const float4* base = reinterpret_cast<const float4*>(
        w + (size_t)(nb * 128) * K_DIM + kb * 128);

    float4 vv[8];
    float a = 0.0f;
    #pragma unroll
    for (int i = 0; i < 8; i++) {
        int idx = i * 512 + t;
        int r   = idx >> 5;
        int c4  = idx & 31;
        vv[i] = __ldg(base + (size_t)r * (K_DIM / 4) + c4);
        a = fmaxf(a, fmaxf(fmaxf(fabsf(vv[i].x), fabsf(vv[i].y)),
                           fmaxf(fabsf(vv[i].z), fabsf(vv[i].w))));
    }
    #pragma unroll
    for (int off = 16; off > 0; off >>= 1)
        a = fmaxf(a, __shfl_xor_sync(0xffffffffu, a, off));
    __shared__ float red[16];
    if ((t & 31) == 0) red[t >> 5] = a;
    __syncthreads();
    float am = red[0];
    #pragma unroll
    for (int i = 1; i < 16; i++) am = fmaxf(am, red[i]);

    float s = fmaxf(__fdiv_rn(am, 127.0f), 1e-12f);

    __half* qbase = g_wq + (size_t)(nb * 128) * K_DIM + kb * 128;
    #pragma unroll
    for (int i = 0; i < 8; i++) {
        int idx = i * 512 + t;
        int r   = idx >> 5;
        int c4  = idx & 31;
        float q0 = fminf(fmaxf(rintf(__fdiv_rn(vv[i].x, s)), -128.0f), 127.0f);
        float q1 = fminf(fmaxf(rintf(__fdiv_rn(vv[i].y, s)), -128.0f), 127.0f);
        float q2 = fminf(fmaxf(rintf(__fdiv_rn(vv[i].z, s)), -128.0f), 127.0f);
        float q3 = fminf(fmaxf(rintf(__fdiv_rn(vv[i].w, s)), -128.0f), 127.0f);
        uint2 h;
        h.x = h2_bits(__floats2half2_rn(q0, q1));
        h.y = h2_bits(__floats2half2_rn(q2, q3));
        *reinterpret_cast<uint2*>(qbase + (size_t)r * K_DIM + c4 * 4) = h;
    }
    if (t == 0) g_ws[nb * KB + kb] = s;
}

// ---------------------------------------------------------------------------
// Kernel 3: fp16 GEMM on quantized values (exact: integer values, fp32
// accumulation, per-128-K-block sums < 2^24). 128x128 CTA tile, K-step 128,
// mma.sync.m16n8k16 + ldmatrix. Grid swizzle GROUP_M=32 (B panel re-read 2x,
// wave set ~37MB L2-hot); spread cp.async; packed f32x2 promotion.
// Mainloop byte-identical to the validated 738.5us kernel.
// ---------------------------------------------------------------------------
#define STAGES     3
#define TILE_BYTES 32768                       // 128 rows x 256 B (fp16)
#define STAGE_SZ   (2 * TILE_BYTES)            // A + B
#define GEMM_SMEM  (STAGES * STAGE_SZ)         // 196608
#define GRID_N     (N_DIM / 128)               // 32
#define GRID_M     (M_DIM / 128)               // 64
#define GROUP_M    32

__device__ __forceinline__ uint32_t smem_u32(const void* p) {
    return (uint32_t)__cvta_generic_to_shared(p);
}
__device__ __forceinline__ void cpa16(uint32_t s, const void* g) {
    asm volatile("cp.async.cg.shared.global [%0], [%1], 16;\n" :: "r"(s), "l"(g));
}
__device__ __forceinline__ void mma_f16(float c[4], const uint32_t a[4],
                                        uint32_t b0, uint32_t b1) {
    asm volatile(
        "mma.sync.aligned.m16n8k16.row.col.f32.f16.f16.f32 "
        "{%0,%1,%2,%3}, {%4,%5,%6,%7}, {%8,%9}, {%0,%1,%2,%3};\n"
        : "+f"(c[0]), "+f"(c[1]), "+f"(c[2]), "+f"(c[3])
        : "r"(a[0]), "r"(a[1]), "r"(a[2]), "r"(a[3]), "r"(b0), "r"(b1));
}
__device__ __forceinline__ void ldsm4(uint32_t r[4], uint32_t addr) {
    asm volatile("ldmatrix.sync.aligned.m8n8.x4.shared.b16 {%0,%1,%2,%3}, [%4];"
                 : "=r"(r[0]), "=r"(r[1]), "=r"(r[2]), "=r"(r[3]) : "r"(addr));
}
__device__ __forceinline__ unsigned long long pack2(float lo, float hi) {
    unsigned long long r;
    asm("mov.b64 %0, {%1, %2};" : "=l"(r) : "f"(lo), "f"(hi));
    return r;
}
__device__ __forceinline__ void unpack2(unsigned long long v, float& lo, float& hi) {
    asm("mov.b64 {%0, %1}, %2;" : "=f"(lo), "=f"(hi) : "l"(v));
}
// packed dual fp32 FMA: d.lo = a.lo*b.lo + d.lo ; d.hi = a.hi*b.hi + d.hi
__device__ __forceinline__ void fma2(unsigned long long& d, unsigned long long a,
                                     unsigned long long b) {
    asm("fma.rn.f32x2 %0, %1, %2, %0;" : "+l"(d) : "l"(a), "l"(b));
}

__global__ void __launch_bounds__(256, 1)
gemm_kernel(const float* __restrict__ bias, float* __restrict__ out) {
    extern __shared__ __align__(1024) char smem[];
    const uint32_t sb = smem_u32(smem);
    const int tid  = threadIdx.x;
    const int lane = tid & 31;
    const int w    = tid >> 5;

    // grid swizzle: 32 m-tiles per group -> B panel re-read 2x from DRAM
    const int pid      = blockIdx.x;
    const int group_id = pid / (GROUP_M * GRID_N);
    const int first_m  = group_id * GROUP_M;
    const int gsize    = min(GRID_M - first_m, GROUP_M);
    const int bm       = first_m + (pid % gsize);
    const int bn       = (pid % (GROUP_M * GRID_N)) / gsize;

    const int m0 = bm * 128;
    const int n0 = bn * 128;
    const int nb = bn;
    const int wm   = w & 3;        // 4 warps along M (32 rows each)
    const int wn   = w >> 2;       // 2 warps along N (64 cols each)
    const int grp  = lane >> 2;    // 0..7
    const int tig  = lane & 3;     // 0..3
    const int j    = lane >> 3;    // ldmatrix matrix index 0..3
    const int rlo  = lane & 7;     // ldmatrix row-in-matrix

    // one 1/8 slice of a stage load (i in 0..7): 2 x cp.async 16B per thread
    auto load_part = [&](int stage, int kb, int i) {
        const __half* Ag = g_xq + (size_t)m0 * K_DIM + kb * 128;
        const __half* Bg = g_wq + (size_t)n0 * K_DIM + kb * 128;
        uint32_t As = sb + stage * STAGE_SZ;
        uint32_t Bs = As + TILE_BYTES;
        int id = i * 256 + tid;        // 0..2047 chunks of 16B
        int r  = id >> 4;              // row 0..127
        int c  = id & 15;              // chunk 0..15
        uint32_t so = r * 256 + (((c & 8) | ((c ^ r) & 7)) << 4);
        cpa16(As + so, Ag + (size_t)r * K_DIM + c * 8);
        cpa16(Bs + so, Bg + (size_t)r * K_DIM + c * 8);
    };
    auto load_stage = [&](int stage, int kb) {
        #pragma unroll
        for (int i = 0; i < 8; i++) load_part(stage, kb, i);
    };

    // fp32 accumulators as packed f32x2 pairs: [fm][fn][2] (lo pair, hi pair)
    unsigned long long facc2[2][8][2];
    #pragma unroll
    for (int i = 0; i < 2; i++)
        #pragma unroll
        for (int jj = 0; jj < 8; jj++) {
            facc2[i][jj][0] = 0ULL;
            facc2[i][jj][1] = 0ULL;
        }

    load_stage(0, 0); asm volatile("cp.async.commit_group;");
    load_stage(1, 1); asm volatile("cp.async.commit_group;");

    // precomputed ldmatrix row bases (within a stage)
    const int arow = wm * 32 + (j & 1) * 8 + rlo;            // + fm*16
    const int brow = wn * 64 + ((j >> 1) << 3) + rlo;        // + fnp*16
    const int achk = (j >> 1);                               // + kk*2
    const int bchk = (j & 1);                                // + kk*2

    for (int kb = 0; kb < KB; kb++) {
        asm volatile("cp.async.wait_group 1;");
        __syncthreads();
        const uint32_t As = sb + (uint32_t)(kb % 3) * STAGE_SZ;
        const uint32_t Bs = As + TILE_BYTES;
        const bool pf = (kb + 2 < KB);
        const int  pfs = (kb + 2) % 3;

        // per-kb combined scales, packed for f32x2 promotion
        const float wsv = g_ws[nb * KB + kb];
        unsigned long long csp[2][2];
        #pragma unroll
        for (int fm = 0; fm < 2; fm++) {
            int r = m0 + wm * 32 + fm * 16 + grp;
            float cs0 = __ldg(&g_xs[(size_t)kb * M_DIM + r])     * wsv;
            float cs1 = __ldg(&g_xs[(size_t)kb * M_DIM + r + 8]) * wsv;
            csp[fm][0] = pack2(cs0, cs0);
            csp[fm][1] = pack2(cs1, cs1);
        }

        float c[2][8][4];
        #pragma unroll
        for (int i = 0; i < 2; i++)
            #pragma unroll
            for (int jj = 0; jj < 8; jj++)
                #pragma unroll
                for (int k = 0; k < 4; k++) c[i][jj][k] = 0.0f;

        #pragma unroll
        for (int kk = 0; kk < 8; kk++) {
            // spread the next-stage global loads across the block (1 slice per kk)
            if (pf) load_part(pfs, kb + 2, kk);

            // A fragments: 2 x ldmatrix.x4 (m16k16 each)
            uint32_t a[2][4];
            #pragma unroll
            for (int fm = 0; fm < 2; fm++) {
                int row = arow + fm * 16;
                int ch  = kk * 2 + achk;
                ldsm4(a[fm], As + row * 256 + (((ch & 8) | ((ch ^ row) & 7)) << 4));
            }
            // B fragments + MMAs: 4 x ldmatrix.x4 (two n8k16 frags each)
            #pragma unroll
            for (int fnp = 0; fnp < 4; fnp++) {
                int row = brow + fnp * 16;
                int ch  = kk * 2 + bchk;
                uint32_t bf[4];
                ldsm4(bf, Bs + row * 256 + (((ch & 8) | ((ch ^ row) & 7)) << 4));
                #pragma unroll
                for (int fm = 0; fm < 2; fm++) {
                    mma_f16(c[fm][fnp * 2],     a[fm], bf[0], bf[1]);
                    mma_f16(c[fm][fnp * 2 + 1], a[fm], bf[2], bf[3]);
                }
            }
        }

        // exact per-kb promotion, packed: facc2 += csp * c (dual IEEE fp32 FMA)
        #pragma unroll
        for (int fm = 0; fm < 2; fm++)
            #pragma unroll
            for (int fn = 0; fn < 8; fn++) {
                fma2(facc2[fm][fn][0], pack2(c[fm][fn][0], c[fm][fn][1]), csp[fm][0]);
                fma2(facc2[fm][fn][1], pack2(c[fm][fn][2], c[fm][fn][3]), csp[fm][1]);
            }

        asm volatile("cp.async.commit_group;");
    }

    // epilogue: unpack, add bias, store fp32
    #pragma unroll
    for (int fm = 0; fm < 2; fm++) {
        int r = m0 + wm * 32 + fm * 16 + grp;
        #pragma unroll
        for (int fn = 0; fn < 8; fn++) {
            int cc = n0 + wn * 64 + fn * 8 + tig * 2;
            float2 b2 = *reinterpret_cast<const float2*>(bias + cc);
            float f0, f1, f2, f3;
            unpack2(facc2[fm][fn][0], f0, f1);
            unpack2(facc2[fm][fn][1], f2, f3);
            float2 o0, o1;
            o0.x = f0 + b2.x;
            o0.y = f1 + b2.y;
            o1.x = f2 + b2.x;
            o1.y = f3 + b2.y;
            *reinterpret_cast<float2*>(out + (size_t)r * N_DIM + cc)       = o0;
            *reinterpret_cast<float2*>(out + (size_t)(r + 8) * N_DIM + cc) = o1;
        }
    }
}

// ---------------------------------------------------------------------------
extern "C" void kernel_launch(void* const* d_in, const int* in_sizes, int n_in,
                              void* d_out, int out_size) {
    const float* x    = (const float*)d_in[0];
    const float* wgt  = (const float*)d_in[1];
    const float* bias = (const float*)d_in[2];
    float* out        = (float*)d_out;

    quant_x_kernel<<<(M_DIM * KB / 4) / 8, 256>>>(x);
    quant_w_kernel<<<NB * KB, 512>>>(wgt);

    cudaFuncSetAttribute(gemm_kernel,
                         cudaFuncAttributeMaxDynamicSharedMemorySize, GEMM_SMEM);
    gemm_kernel<<<GRID_M * GRID_N, 256, GEMM_SMEM>>>(bias, out);
}